// round 7
// baseline (speedup 1.0000x reference)
#include <cuda_runtime.h>
#include <cstdint>
#include <math.h>

#define T_SEQ   4096
#define NNODES  64
#define FPL     8
#define OBS_DIM 512
#define HID     64
#define GATES   256
#define FULLMASK 0xffffffffu

// scratch (static device allocations — allowed)
__device__ float g_hs[T_SEQ * NNODES * HID];   // 64 MB: h[t][n][k]
__device__ float g_Wg_t[HID * GATES];
__device__ float g_Wm_t[GATES * HID];
__device__ float g_Ws_t[GATES * HID];

typedef unsigned long long ull;
typedef unsigned int u32;

__device__ __forceinline__ void ffma2(ull& d, const ull a, const ull b) {
    asm("fma.rn.f32x2 %0, %1, %2, %0;" : "+l"(d) : "l"(a), "l"(b));
}
__device__ __forceinline__ ull addf2(ull a, ull b) {
    ull r; asm("add.rn.f32x2 %0, %1, %2;" : "=l"(r) : "l"(a), "l"(b)); return r;
}
__device__ __forceinline__ float2 unpack2(ull v) {
    float2 f; asm("mov.b64 {%0, %1}, %2;" : "=f"(f.x), "=f"(f.y) : "l"(v)); return f;
}
__device__ __forceinline__ ull pack2(float lo, float hi) {
    ull v; asm("mov.b64 %0, {%1, %2};" : "=l"(v) : "f"(lo), "f"(hi)); return v;
}
__device__ __forceinline__ float tanh_mufu(float x) {
    float r; asm("tanh.approx.f32 %0, %1;" : "=f"(r) : "f"(x)); return r;
}
__device__ __forceinline__ u32 smem_u32(const void* p) {
    u32 a;
    asm("{ .reg .u64 t; cvta.to.shared.u64 t, %1; cvt.u32.u64 %0, t; }"
        : "=r"(a) : "l"(p));
    return a;
}

// ---------------------------------------------------------------------------
// Kernel A: one-time weight transposes for head GEMVs
// ---------------------------------------------------------------------------
__global__ void transpose_kernel(const float* __restrict__ Wg,
                                 const float* __restrict__ Wm,
                                 const float* __restrict__ Ws)
{
    int i = blockIdx.x * 256 + threadIdx.x;
    if (i < GATES * HID) {
        int j = i >> 6, k = i & 63;
        g_Wg_t[k * GATES + j] = Wg[i];
        int a = i >> 8, jj = i & 255;
        g_Wm_t[jj * HID + a] = Wm[i];
        g_Ws_t[jj * HID + a] = Ws[i];
    }
}

// ---------------------------------------------------------------------------
// Kernel B: LSTMs. 32 CTAs x 256 threads; each CTA runs TWO nodes that SHARE
// the per-thread weight registers (weights are node-independent). One barrier
// per step covers both nodes; node B's FFMA chain fills node A's dep stalls.
// Thread tid -> (k = tid>>2, gate = tid&3), row r = gate*64 + k.
// Activation via MUFU.TANH: sigma(z) = 0.5 + 0.5*tanh(z/2) (weights
// pre-scaled by 0.5); gate g uses tanh directly (scale 1).
// Predicated (@p) STS/STG stores: no BSSY/BSYNC in the loop body.
// ---------------------------------------------------------------------------
__global__ void __launch_bounds__(256, 1)
lstm_kernel(const float* __restrict__ x,
            const float* __restrict__ W_ih,
            const float* __restrict__ W_hh,
            const float* __restrict__ b_ih,
            const float* __restrict__ b_hh,
            float* __restrict__ out)
{
    const int nA   = blockIdx.x * 2;
    const int tid  = threadIdx.x;
    const int k    = tid >> 2;
    const int gate = tid & 3;
    const int r    = gate * HID + k;
    const unsigned lane = tid & 31u;
    const unsigned lb   = lane & ~3u;

    const bool  is_g = (gate == 2);
    const float m    = is_g ? 1.0f : 0.5f;
    const float Aact = is_g ? 1.0f : 0.5f;
    const float Bact = is_g ? 0.0f : 0.5f;

    // h2[parity][node][k]: node A/B slices 256B apart for immediate-offset STS
    __shared__ __align__(16) float h2[2][2][HID];
    __shared__ __align__(16) float xs[2][2][32][FPL];   // [buf][node][s][j]

    // weights in registers, pre-scaled by m, packed f32x2 — SHARED by A and B
    ull whh[32];
    {
        const float* wrow = W_hh + r * HID;
#pragma unroll
        for (int i = 0; i < 32; i++)
            whh[i] = pack2(wrow[2*i] * m, wrow[2*i+1] * m);
    }
    ull wih[4];
    {
        const float* wrow = W_ih + r * FPL;
#pragma unroll
        for (int i = 0; i < 4; i++)
            wih[i] = pack2(wrow[2*i] * m, wrow[2*i+1] * m);
    }
    const float bsum = (b_ih[r] + b_hh[r]) * m;

    const u32 h2_base = smem_u32(h2);
    float cA = 0.0f, cB = 0.0f;
    if (tid < HID) { h2[0][0][tid] = 0.0f; h2[0][1][tid] = 0.0f; }

    // prologue: stage x batch 0 for both nodes
    {
        int s = tid >> 3, j = tid & 7;
        xs[0][0][s][j] = x[s * OBS_DIM + nA * FPL + j];
        xs[0][1][s][j] = x[s * OBS_DIM + (nA + 1) * FPL + j];
    }
    __syncthreads();

    // g_hs pointer (node A; node B = +HID floats = +256B immediate)
    const float* hs_ptr = g_hs + nA * HID + k;

    for (int b = 0; b < T_SEQ / 32; b++) {
        // prefetch next x batch (both nodes) into registers
        float xpA = 0.0f, xpB = 0.0f;
        {
            int tn = (b + 1) * 32 + (tid >> 3);
            if (tn < T_SEQ) {
                xpA = x[tn * OBS_DIM + nA * FPL + (tid & 7)];
                xpB = x[tn * OBS_DIM + (nA + 1) * FPL + (tid & 7)];
            }
        }
#pragma unroll 4
        for (int s = 0; s < 32; s++) {
            const int par = s & 1;

            // ---- node A accumulation ----
            ull a0 = pack2(bsum, 0.0f), a1 = 0, a2 = 0, a3 = 0;
            ull a4 = 0, a5 = 0, a6 = 0, a7 = 0;
            // ---- node B accumulation (independent chain) ----
            ull e0 = pack2(bsum, 0.0f), e1 = 0, e2 = 0, e3 = 0;
            ull e4 = 0, e5 = 0, e6 = 0, e7 = 0;
            {
                const ulonglong2* xpa = (const ulonglong2*)xs[b & 1][0][s];
                const ulonglong2* xpb = (const ulonglong2*)xs[b & 1][1][s];
                ulonglong2 xa0 = xpa[0], xa1 = xpa[1];
                ulonglong2 xb0 = xpb[0], xb1 = xpb[1];
                ffma2(a0, wih[0], xa0.x); ffma2(e0, wih[0], xb0.x);
                ffma2(a2, wih[1], xa0.y); ffma2(e2, wih[1], xb0.y);
                ffma2(a4, wih[2], xa1.x); ffma2(e4, wih[2], xb1.x);
                ffma2(a6, wih[3], xa1.y); ffma2(e6, wih[3], xb1.y);
            }
            const ulonglong2* hpA = (const ulonglong2*)h2[par][0];
            const ulonglong2* hpB = (const ulonglong2*)h2[par][1];
#pragma unroll
            for (int mm = 0; mm < 4; mm++) {
                ulonglong2 ha0 = hpA[4*mm + 0], ha1 = hpA[4*mm + 1];
                ulonglong2 ha2 = hpA[4*mm + 2], ha3 = hpA[4*mm + 3];
                ulonglong2 hb0 = hpB[4*mm + 0], hb1 = hpB[4*mm + 1];
                ulonglong2 hb2 = hpB[4*mm + 2], hb3 = hpB[4*mm + 3];
                ffma2(a0, whh[8*mm+0], ha0.x); ffma2(e0, whh[8*mm+0], hb0.x);
                ffma2(a1, whh[8*mm+1], ha0.y); ffma2(e1, whh[8*mm+1], hb0.y);
                ffma2(a2, whh[8*mm+2], ha1.x); ffma2(e2, whh[8*mm+2], hb1.x);
                ffma2(a3, whh[8*mm+3], ha1.y); ffma2(e3, whh[8*mm+3], hb1.y);
                ffma2(a4, whh[8*mm+4], ha2.x); ffma2(e4, whh[8*mm+4], hb2.x);
                ffma2(a5, whh[8*mm+5], ha2.y); ffma2(e5, whh[8*mm+5], hb2.y);
                ffma2(a6, whh[8*mm+6], ha3.x); ffma2(e6, whh[8*mm+6], hb3.x);
                ffma2(a7, whh[8*mm+7], ha3.y); ffma2(e7, whh[8*mm+7], hb3.y);
            }
            // reductions
            float2 fA = unpack2(addf2(addf2(addf2(a0, a1), addf2(a2, a3)),
                                      addf2(addf2(a4, a5), addf2(a6, a7))));
            float2 fB = unpack2(addf2(addf2(addf2(e0, e1), addf2(e2, e3)),
                                      addf2(addf2(e4, e5), addf2(e6, e7))));
            const float zA = fA.x + fA.y;
            const float zB = fB.x + fB.y;

            // activation: v = A*tanh(z) + B  (MUFU.TANH, branch-free)
            const float vA = fmaf(tanh_mufu(zA), Aact, Bact);
            const float vB = fmaf(tanh_mufu(zB), Aact, Bact);

            // gather i,f,g,o within the quad (8 independent shuffles)
            const float iA = __shfl_sync(FULLMASK, vA, lb);
            const float fAg = __shfl_sync(FULLMASK, vA, lb | 1);
            const float gA = __shfl_sync(FULLMASK, vA, lb | 2);
            const float oA = __shfl_sync(FULLMASK, vA, lb | 3);
            const float iB = __shfl_sync(FULLMASK, vB, lb);
            const float fBg = __shfl_sync(FULLMASK, vB, lb | 1);
            const float gB = __shfl_sync(FULLMASK, vB, lb | 2);
            const float oB = __shfl_sync(FULLMASK, vB, lb | 3);

            // all lanes compute c/h (quad-identical) — no branch
            cA = fAg * cA + iA * gA;
            cB = fBg * cB + iB * gB;
            const float hA = oA * tanh_mufu(cA);
            const float hB = oB * tanh_mufu(cB);

            // predicated stores: gate==0 lanes commit both nodes
            {
                const u32 aAddr = h2_base + (u32)(((par ^ 1) * 2 * HID + k) * 4);
                asm volatile(
                    "{ .reg .pred p; setp.eq.s32 p, %0, 0;\n\t"
                    "@p st.shared.f32 [%1], %2;\n\t"
                    "@p st.shared.f32 [%1+256], %3;\n\t"
                    "@p st.global.f32 [%4], %2;\n\t"
                    "@p st.global.f32 [%4+256], %3; }"
                    :: "r"(gate), "r"(aAddr), "f"(hA), "f"(hB), "l"(hs_ptr)
                    : "memory");
            }
            hs_ptr += NNODES * HID;

            // stage next x batch mid-way (write-only buffers this batch)
            if (s == 20) {
                xs[(b + 1) & 1][0][tid >> 3][tid & 7] = xpA;
                xs[(b + 1) & 1][1][tid >> 3][tid & 7] = xpB;
            }
            __syncthreads();
        }
    }

    // hn / cn (t=4095 wrote parity (4095&1)^1 = 0)
    if (gate == 0) {
        const int base = 2 * T_SEQ * NNODES;
        out[base + nA * HID + k]       = h2[0][0][k];
        out[base + (nA + 1) * HID + k] = h2[0][1][k];
        out[base + NNODES * HID + nA * HID + k]       = cA;
        out[base + NNODES * HID + (nA + 1) * HID + k] = cB;
    }
}

// ---------------------------------------------------------------------------
// Kernel C: warp-autonomous head. 512 CTAs x 8 warps; one warp per timestep.
// GAT collapses to identity-attention; mean-pool commutes with W_gat.
// ---------------------------------------------------------------------------
__global__ void __launch_bounds__(256, 2)
head_kernel(const float* __restrict__ b_gat,
            const float* __restrict__ b_mean,
            const float* __restrict__ b_std,
            float* __restrict__ out)
{
    const int w    = threadIdx.x >> 5;
    const int lane = threadIdx.x & 31;
    const int t    = blockIdx.x * 8 + w;

    __shared__ __align__(16) float hb[8][HID];
    __shared__ __align__(16) float gs[8][GATES];

    {
        const float* p = g_hs + (long)t * (NNODES * HID);
        float s0 = 0.0f, s1 = 0.0f;
#pragma unroll 8
        for (int n = 0; n < NNODES; n++) {
            s0 += p[n * HID + lane];
            s1 += p[n * HID + 32 + lane];
        }
        hb[w][lane]      = s0 * (1.0f / 64.0f);
        hb[w][32 + lane] = s1 * (1.0f / 64.0f);
    }
    __syncwarp();

#pragma unroll
    for (int i = 0; i < 8; i++) {
        const int j = i * 32 + lane;
        float acc = b_gat[j];
#pragma unroll 8
        for (int k = 0; k < HID; k++)
            acc += g_Wg_t[k * GATES + j] * hb[w][k];
        gs[w][j] = fmaxf(acc, 0.0f);
    }
    __syncwarp();

#pragma unroll
    for (int i = 0; i < 2; i++) {
        const int a = i * 32 + lane;
        float am = b_mean[a], as = b_std[a];
#pragma unroll 8
        for (int j = 0; j < GATES; j++) {
            const float gv = gs[w][j];
            am += g_Wm_t[j * HID + a] * gv;
            as += g_Ws_t[j * HID + a] * gv;
        }
        out[t * NNODES + a] = am;
        float sp = (as > 20.0f) ? as : log1pf(__expf(as));
        out[T_SEQ * NNODES + t * NNODES + a] = fminf(fmaxf(sp, 0.001f), 10.0f);
    }
}

// ---------------------------------------------------------------------------
// launch
// ---------------------------------------------------------------------------
extern "C" void kernel_launch(void* const* d_in, const int* in_sizes, int n_in,
                              void* d_out, int out_size)
{
    const float* x      = (const float*)d_in[0];
    const float* W_ih   = (const float*)d_in[1];
    const float* W_hh   = (const float*)d_in[2];
    const float* b_ih   = (const float*)d_in[3];
    const float* b_hh   = (const float*)d_in[4];
    const float* W_gat  = (const float*)d_in[5];
    // d_in[6], d_in[7] (att_src/att_dst) provably unused: identity adjacency
    // -> softmax over a single unmasked element == 1 for any logits.
    const float* b_gat  = (const float*)d_in[8];
    const float* b_mean = (const float*)d_in[10];
    const float* b_std  = (const float*)d_in[12];
    float* out = (float*)d_out;

    transpose_kernel<<<64, 256>>>(W_gat, (const float*)d_in[9], (const float*)d_in[11]);
    lstm_kernel<<<NNODES / 2, 256>>>(x, W_ih, W_hh, b_ih, b_hh, out);
    head_kernel<<<T_SEQ / 8, 256>>>(b_gat, b_mean, b_std, out);
}

// round 8
// speedup vs baseline: 1.5979x; 1.5979x over previous
#include <cuda_runtime.h>
#include <cstdint>
#include <math.h>

#define T_SEQ   4096
#define NNODES  64
#define FPL     8
#define OBS_DIM 512
#define HID     64
#define GATES   256
#define FULLMASK 0xffffffffu

// scratch (static device allocations — allowed)
__device__ float g_hs[T_SEQ * NNODES * HID];   // 64 MB: h[t][n][k]
__device__ float g_Wg_t[HID * GATES];
__device__ float g_Wm_t[GATES * HID];
__device__ float g_Ws_t[GATES * HID];

typedef unsigned long long ull;
typedef unsigned int u32;

__device__ __forceinline__ void ffma2(ull& d, const ull a, const ull b) {
    asm("fma.rn.f32x2 %0, %1, %2, %0;" : "+l"(d) : "l"(a), "l"(b));
}
__device__ __forceinline__ ull addf2(ull a, ull b) {
    ull r; asm("add.rn.f32x2 %0, %1, %2;" : "=l"(r) : "l"(a), "l"(b)); return r;
}
__device__ __forceinline__ float2 unpack2(ull v) {
    float2 f; asm("mov.b64 {%0, %1}, %2;" : "=f"(f.x), "=f"(f.y) : "l"(v)); return f;
}
__device__ __forceinline__ ull pack2(float lo, float hi) {
    ull v; asm("mov.b64 %0, {%1, %2};" : "=l"(v) : "f"(lo), "f"(hi)); return v;
}
__device__ __forceinline__ float tanh_mufu(float x) {
    float r; asm("tanh.approx.f32 %0, %1;" : "=f"(r) : "f"(x)); return r;
}
__device__ __forceinline__ u32 smem_u32(const void* p) {
    u32 a;
    asm("{ .reg .u64 t; cvta.to.shared.u64 t, %1; cvt.u32.u64 %0, t; }"
        : "=r"(a) : "l"(p));
    return a;
}

// ---------------------------------------------------------------------------
// Kernel A: one-time weight transposes for head GEMVs
// ---------------------------------------------------------------------------
__global__ void transpose_kernel(const float* __restrict__ Wg,
                                 const float* __restrict__ Wm,
                                 const float* __restrict__ Ws)
{
    int i = blockIdx.x * 256 + threadIdx.x;
    if (i < GATES * HID) {
        int j = i >> 6, k = i & 63;
        g_Wg_t[k * GATES + j] = Wg[i];
        int a = i >> 8, jj = i & 255;
        g_Wm_t[jj * HID + a] = Wm[i];
        g_Ws_t[jj * HID + a] = Ws[i];
    }
}

// ---------------------------------------------------------------------------
// Kernel B: 64 independent LSTMs, one CTA per node, 256 threads, T=4096.
// Thread tid -> (k = tid>>2, gate = tid&3), row r = gate*64 + k.
// (R6 winner structure; only the activation path changed to MUFU.TANH.)
// Activation: sigma(z) = 0.5 + 0.5*tanh(z/2) with weights pre-scaled by 0.5;
// gate g uses tanh directly (scale 1). One MUFU + one FMA per activation.
// All lanes redundantly compute c/h (quad-identical); stores are inline-asm
// predicated (@p STS/STG) so ptxas emits NO BSSY/BSYNC in the loop body.
// ---------------------------------------------------------------------------
__global__ void __launch_bounds__(256, 1)
lstm_kernel(const float* __restrict__ x,
            const float* __restrict__ W_ih,
            const float* __restrict__ W_hh,
            const float* __restrict__ b_ih,
            const float* __restrict__ b_hh,
            float* __restrict__ out)
{
    const int n    = blockIdx.x;
    const int tid  = threadIdx.x;
    const int k    = tid >> 2;
    const int gate = tid & 3;
    const int r    = gate * HID + k;
    const unsigned lane = tid & 31u;
    const unsigned lb   = lane & ~3u;

    const bool  is_g = (gate == 2);
    const float m    = is_g ? 1.0f : 0.5f;   // tanh(z) vs 0.5+0.5*tanh(z/2)
    const float Aact = is_g ? 1.0f : 0.5f;
    const float Bact = is_g ? 0.0f : 0.5f;

    __shared__ __align__(16) float h2[2][HID];
    __shared__ __align__(16) float xs[2][32][FPL];

    // weights in registers, pre-scaled by m, packed f32x2
    ull whh[32];
    {
        const float* wrow = W_hh + r * HID;
#pragma unroll
        for (int i = 0; i < 32; i++)
            whh[i] = pack2(wrow[2*i] * m, wrow[2*i+1] * m);
    }
    ull wih[4];
    {
        const float* wrow = W_ih + r * FPL;
#pragma unroll
        for (int i = 0; i < 4; i++)
            wih[i] = pack2(wrow[2*i] * m, wrow[2*i+1] * m);
    }
    const float bsum = (b_ih[r] + b_hh[r]) * m;

    const u32 h2_base = smem_u32(h2);       // smem address of h2[0][0]
    float c_reg = 0.0f;
    if (tid < HID) h2[0][tid] = 0.0f;

    // prologue: stage x batch 0
    {
        int s = tid >> 3, j = tid & 7;
        xs[0][s][j] = x[s * OBS_DIM + n * FPL + j];
    }
    __syncthreads();

    // g_hs write pointer for this thread (gate-0 lanes are the real writers)
    const float* hs_ptr = g_hs + n * HID + k;

    for (int b = 0; b < T_SEQ / 32; b++) {
        // prefetch next x batch into a register (hidden over 32 steps)
        float xpref = 0.0f;
        {
            int tn = (b + 1) * 32 + (tid >> 3);
            if (tn < T_SEQ) xpref = x[tn * OBS_DIM + n * FPL + (tid & 7)];
        }
#pragma unroll 4
        for (int s = 0; s < 32; s++) {
            const int par = s & 1;

            // acc = m*(bias + W_ih·x + W_hh·h)   (8 packed accumulators)
            ull a0 = pack2(bsum, 0.0f), a1 = 0, a2 = 0, a3 = 0;
            ull a4 = 0, a5 = 0, a6 = 0, a7 = 0;
            {
                const ulonglong2* xp = (const ulonglong2*)xs[b & 1][s];
                ulonglong2 xv0 = xp[0], xv1 = xp[1];
                ffma2(a0, wih[0], xv0.x);
                ffma2(a2, wih[1], xv0.y);
                ffma2(a4, wih[2], xv1.x);
                ffma2(a6, wih[3], xv1.y);
            }
            const ulonglong2* hp = (const ulonglong2*)h2[par];
#pragma unroll
            for (int mm = 0; mm < 4; mm++) {
                ulonglong2 hv0 = hp[4*mm + 0], hv1 = hp[4*mm + 1];
                ulonglong2 hv2 = hp[4*mm + 2], hv3 = hp[4*mm + 3];
                ffma2(a0, whh[8*mm+0], hv0.x);
                ffma2(a1, whh[8*mm+1], hv0.y);
                ffma2(a2, whh[8*mm+2], hv1.x);
                ffma2(a3, whh[8*mm+3], hv1.y);
                ffma2(a4, whh[8*mm+4], hv2.x);
                ffma2(a5, whh[8*mm+5], hv2.y);
                ffma2(a6, whh[8*mm+6], hv3.x);
                ffma2(a7, whh[8*mm+7], hv3.y);
            }
            // packed reduction tree
            ull b0 = addf2(a0, a1), b1 = addf2(a2, a3);
            ull b2 = addf2(a4, a5), b3 = addf2(a6, a7);
            float2 f = unpack2(addf2(addf2(b0, b1), addf2(b2, b3)));
            const float accv = f.x + f.y;

            // activation: v = A*tanh(z) + B  (MUFU.TANH, branch-free)
            const float v = fmaf(tanh_mufu(accv), Aact, Bact);

            // gather i,f,g,o within the quad (independent shuffles)
            const float vi = __shfl_sync(FULLMASK, v, lb);
            const float vf = __shfl_sync(FULLMASK, v, lb | 1);
            const float vg = __shfl_sync(FULLMASK, v, lb | 2);
            const float vo = __shfl_sync(FULLMASK, v, lb | 3);

            // ALL lanes compute c/h (identical within the quad) — no branch
            c_reg = vf * c_reg + vi * vg;
            const float h = vo * tanh_mufu(c_reg);

            // predicated stores (no BSSY/BSYNC): only gate==0 lanes commit
            {
                const u32 sts_addr = h2_base + (u32)((((par ^ 1) * HID) + k) * 4);
                asm volatile(
                    "{ .reg .pred p; setp.eq.s32 p, %0, 0;\n\t"
                    "@p st.shared.f32 [%1], %3;\n\t"
                    "@p st.global.f32 [%2], %3; }"
                    :: "r"(gate), "r"(sts_addr), "l"(hs_ptr), "f"(h)
                    : "memory");
            }
            hs_ptr += NNODES * HID;

            // stage next x batch mid-way (write-only buffer this batch)
            if (s == 20) xs[(b + 1) & 1][tid >> 3][tid & 7] = xpref;
            __syncthreads();
        }
    }

    // hn / cn (t=4095 wrote parity (4095&1)^1 = h2[0])
    if (gate == 0) {
        const int base = 2 * T_SEQ * NNODES;
        out[base + n * HID + k] = h2[0][k];
        out[base + NNODES * HID + n * HID + k] = c_reg;
    }
}

// ---------------------------------------------------------------------------
// Kernel C: warp-autonomous head. 512 CTAs x 8 warps; one warp per timestep.
// GAT collapses to identity-attention; mean-pool commutes with W_gat.
// ---------------------------------------------------------------------------
__global__ void __launch_bounds__(256, 2)
head_kernel(const float* __restrict__ b_gat,
            const float* __restrict__ b_mean,
            const float* __restrict__ b_std,
            float* __restrict__ out)
{
    const int w    = threadIdx.x >> 5;
    const int lane = threadIdx.x & 31;
    const int t    = blockIdx.x * 8 + w;

    __shared__ __align__(16) float hb[8][HID];
    __shared__ __align__(16) float gs[8][GATES];

    {
        const float* p = g_hs + (long)t * (NNODES * HID);
        float s0 = 0.0f, s1 = 0.0f;
#pragma unroll 8
        for (int n = 0; n < NNODES; n++) {
            s0 += p[n * HID + lane];
            s1 += p[n * HID + 32 + lane];
        }
        hb[w][lane]      = s0 * (1.0f / 64.0f);
        hb[w][32 + lane] = s1 * (1.0f / 64.0f);
    }
    __syncwarp();

#pragma unroll
    for (int i = 0; i < 8; i++) {
        const int j = i * 32 + lane;
        float acc = b_gat[j];
#pragma unroll 8
        for (int k = 0; k < HID; k++)
            acc += g_Wg_t[k * GATES + j] * hb[w][k];
        gs[w][j] = fmaxf(acc, 0.0f);
    }
    __syncwarp();

#pragma unroll
    for (int i = 0; i < 2; i++) {
        const int a = i * 32 + lane;
        float am = b_mean[a], as = b_std[a];
#pragma unroll 8
        for (int j = 0; j < GATES; j++) {
            const float gv = gs[w][j];
            am += g_Wm_t[j * HID + a] * gv;
            as += g_Ws_t[j * HID + a] * gv;
        }
        out[t * NNODES + a] = am;
        float sp = (as > 20.0f) ? as : log1pf(__expf(as));
        out[T_SEQ * NNODES + t * NNODES + a] = fminf(fmaxf(sp, 0.001f), 10.0f);
    }
}

// ---------------------------------------------------------------------------
// launch
// ---------------------------------------------------------------------------
extern "C" void kernel_launch(void* const* d_in, const int* in_sizes, int n_in,
                              void* d_out, int out_size)
{
    const float* x      = (const float*)d_in[0];
    const float* W_ih   = (const float*)d_in[1];
    const float* W_hh   = (const float*)d_in[2];
    const float* b_ih   = (const float*)d_in[3];
    const float* b_hh   = (const float*)d_in[4];
    const float* W_gat  = (const float*)d_in[5];
    // d_in[6], d_in[7] (att_src/att_dst) provably unused: identity adjacency
    // -> softmax over a single unmasked element == 1 for any logits.
    const float* b_gat  = (const float*)d_in[8];
    const float* b_mean = (const float*)d_in[10];
    const float* b_std  = (const float*)d_in[12];
    float* out = (float*)d_out;

    transpose_kernel<<<64, 256>>>(W_gat, (const float*)d_in[9], (const float*)d_in[11]);
    lstm_kernel<<<NNODES, 256>>>(x, W_ih, W_hh, b_ih, b_hh, out);
    head_kernel<<<T_SEQ / 8, 256>>>(b_gat, b_mean, b_std, out);
}